// round 1
// baseline (speedup 1.0000x reference)
#include <cuda_runtime.h>
#include <math.h>
#include <stdint.h>

// ---------------- problem constants ----------------
#define Dm   768
#define Hh   12
#define HDm  64
#define Mm   3072
#define Lm   12
#define Em   8
#define Km   2
#define Bm   32
#define Sm   196
#define GSm  392
#define NGm  16          // number of MoE groups = B*S/GS
#define CAPm 98          // expert capacity per group
#define NTOK (Bm*Sm)     // 6272
#define EROWS (NGm*CAPm) // 1568 rows per expert
#define TROWS (Em*EROWS) // 12544 total dispatched rows

// ---------------- scratch (device globals; no allocation allowed) ----------
__device__ float g_x  [(size_t)NTOK*Dm];
__device__ float g_h  [(size_t)NTOK*Dm];
__device__ float g_q  [(size_t)NTOK*Dm];
__device__ float g_k  [(size_t)NTOK*Dm];
__device__ float g_v  [(size_t)NTOK*Dm];
__device__ float g_ao [(size_t)NTOK*Dm];
__device__ float g_mlp[(size_t)NTOK*Mm];
__device__ float g_buf[(size_t)TROWS*Dm];
__device__ float g_hex[(size_t)TROWS*Mm];
__device__ float g_y  [(size_t)TROWS*Dm];
__device__ int   g_slot_src[TROWS];
__device__ int   g_comb_idx[NTOK*Km];
__device__ float g_comb_gate[NTOK*Km];

// ---------------- helpers ----------------
__device__ __forceinline__ float gelu_f(float x) {
    const float c = 0.7978845608028654f; // sqrt(2/pi)
    float t = tanhf(c * (x + 0.044715f * x * x * x));
    return 0.5f * x * (1.0f + t);
}

__device__ __forceinline__ unsigned long long pack2(float x, float y) {
    unsigned long long r;
    asm("mov.b64 %0, {%1, %2};" : "=l"(r) : "f"(x), "f"(y));
    return r;
}
__device__ __forceinline__ void unpack2(unsigned long long v, float& x, float& y) {
    asm("mov.b64 {%0, %1}, %2;" : "=f"(x), "=f"(y) : "l"(v));
}
__device__ __forceinline__ unsigned long long fma2(unsigned long long a,
                                                   unsigned long long b,
                                                   unsigned long long c) {
    unsigned long long d;
    asm("fma.rn.f32x2 %0, %1, %2, %3;" : "=l"(d) : "l"(a), "l"(b), "l"(c));
    return d;
}

__device__ __forceinline__ float block_reduce_sum(float v) {
    __shared__ float sh[33];
    int lane = threadIdx.x & 31, w = threadIdx.x >> 5;
    #pragma unroll
    for (int o = 16; o; o >>= 1) v += __shfl_xor_sync(0xffffffffu, v, o);
    if (lane == 0) sh[w] = v;
    __syncthreads();
    int nw = blockDim.x >> 5;
    float r = (threadIdx.x < nw) ? sh[threadIdx.x] : 0.0f;
    if (w == 0) {
        #pragma unroll
        for (int o = 16; o; o >>= 1) r += __shfl_xor_sync(0xffffffffu, r, o);
        if (lane == 0) sh[32] = r;
    }
    __syncthreads();
    float out = sh[32];
    __syncthreads();
    return out;
}

// ---------------- elementwise kernels ----------------
__global__ void addpos_kernel(const float* __restrict__ x,
                              const float* __restrict__ pe,
                              float* __restrict__ out) {
    int i = blockIdx.x * blockDim.x + threadIdx.x;
    if (i < NTOK * Dm) out[i] = x[i] + pe[i % (Sm * Dm)];
}

__global__ void ln_kernel(const float* __restrict__ in, float* __restrict__ out,
                          const float* __restrict__ s, const float* __restrict__ b) {
    int t = blockIdx.x;
    const float* xr = in + (size_t)t * Dm;
    float sum = 0.0f;
    for (int i = threadIdx.x; i < Dm; i += blockDim.x) sum += xr[i];
    float mu = block_reduce_sum(sum) * (1.0f / Dm);
    float vs = 0.0f;
    for (int i = threadIdx.x; i < Dm; i += blockDim.x) {
        float d = xr[i] - mu; vs += d * d;
    }
    float var = block_reduce_sum(vs) * (1.0f / Dm);
    float inv = rsqrtf(var + 1e-6f);
    float* orow = out + (size_t)t * Dm;
    for (int i = threadIdx.x; i < Dm; i += blockDim.x)
        orow[i] = (xr[i] - mu) * inv * s[i] + b[i];
}

// ---------------- SGEMM: C[N,P] = act((A@W + bias)*alpha) [store|add] -------
// 128x128 tile, BK=8, 256 threads, 8x8 per thread via fma.rn.f32x2
__global__ void sgemm_kernel(const float* __restrict__ A, const float* __restrict__ W,
                             const float* __restrict__ bias, float* __restrict__ C,
                             int Nrows, int Kd, int Pc,
                             long sA, long sW, long sBias, long sC,
                             float alpha, int act, int accum) {
    int z = blockIdx.z;
    A += (long)z * sA; W += (long)z * sW; C += (long)z * sC;
    const float* Bp = bias ? bias + (long)z * sBias : nullptr;

    __shared__ float As[8][128];
    __shared__ float Bs[8][128];

    int tid = threadIdx.x;
    int row0 = blockIdx.y * 128;
    int col0 = blockIdx.x * 128;
    int ty = tid >> 4;     // 0..15
    int tx = tid & 15;     // 0..15

    unsigned long long acc2[8][4];
    #pragma unroll
    for (int i = 0; i < 8; i++)
        #pragma unroll
        for (int j = 0; j < 4; j++) acc2[i][j] = 0ull;

    int a_r = tid >> 1;          // 0..127
    int a_k = (tid & 1) * 4;     // 0 or 4
    int b_k = tid >> 5;          // 0..7
    int b_c = (tid & 31) * 4;    // 0..124

    for (int k0 = 0; k0 < Kd; k0 += 8) {
        float4 av;
        int gr = row0 + a_r;
        if (gr < Nrows)
            av = *reinterpret_cast<const float4*>(A + (long)gr * Kd + k0 + a_k);
        else
            av = make_float4(0.f, 0.f, 0.f, 0.f);
        As[a_k + 0][a_r] = av.x; As[a_k + 1][a_r] = av.y;
        As[a_k + 2][a_r] = av.z; As[a_k + 3][a_r] = av.w;

        float4 bv = *reinterpret_cast<const float4*>(W + (long)(k0 + b_k) * Pc + col0 + b_c);
        *reinterpret_cast<float4*>(&Bs[b_k][b_c]) = bv;
        __syncthreads();

        #pragma unroll
        for (int kk = 0; kk < 8; kk++) {
            float4 a0 = *reinterpret_cast<const float4*>(&As[kk][ty * 8]);
            float4 a1 = *reinterpret_cast<const float4*>(&As[kk][ty * 8 + 4]);
            const unsigned long long* bp =
                reinterpret_cast<const unsigned long long*>(&Bs[kk][tx * 8]);
            unsigned long long b0 = bp[0], b1 = bp[1], b2 = bp[2], b3 = bp[3];
            float af[8] = {a0.x, a0.y, a0.z, a0.w, a1.x, a1.y, a1.z, a1.w};
            #pragma unroll
            for (int i = 0; i < 8; i++) {
                unsigned long long aa = pack2(af[i], af[i]);
                acc2[i][0] = fma2(aa, b0, acc2[i][0]);
                acc2[i][1] = fma2(aa, b1, acc2[i][1]);
                acc2[i][2] = fma2(aa, b2, acc2[i][2]);
                acc2[i][3] = fma2(aa, b3, acc2[i][3]);
            }
        }
        __syncthreads();
    }

    #pragma unroll
    for (int i = 0; i < 8; i++) {
        int gr = row0 + ty * 8 + i;
        if (gr >= Nrows) continue;
        float* Crow = C + (long)gr * Pc + col0 + tx * 8;
        #pragma unroll
        for (int j = 0; j < 4; j++) {
            float v0, v1;
            unpack2(acc2[i][j], v0, v1);
            int gc = col0 + tx * 8 + 2 * j;
            if (Bp) { v0 += Bp[gc]; v1 += Bp[gc + 1]; }
            v0 *= alpha; v1 *= alpha;
            if (act) { v0 = gelu_f(v0); v1 = gelu_f(v1); }
            if (accum) { Crow[2 * j] += v0; Crow[2 * j + 1] += v1; }
            else       { Crow[2 * j]  = v0; Crow[2 * j + 1]  = v1; }
        }
    }
}

// ---------------- attention: softmax(q k^T) v per (b,h) ----------------
#define KPAD (HDm + 1)
__global__ void attn_kernel(const float* __restrict__ q, const float* __restrict__ k,
                            const float* __restrict__ v, float* __restrict__ o) {
    extern __shared__ float sm[];
    float* Ks = sm;                 // [Sm][KPAD]
    float* Vs = sm + Sm * KPAD;     // [Sm][KPAD]
    __shared__ float att[8][Sm];
    __shared__ float qrow[8][HDm];

    int bh = blockIdx.x;
    int b = bh / Hh, h = bh % Hh;
    int tid = threadIdx.x, warp = tid >> 5, lane = tid & 31;
    const long base = (long)(b * Sm) * Dm + h * HDm;

    for (int idx = tid; idx < Sm * HDm; idx += blockDim.x) {
        int j = idx >> 6, c = idx & 63;
        Ks[j * KPAD + c] = k[base + (long)j * Dm + c];
        Vs[j * KPAD + c] = v[base + (long)j * Dm + c];
    }
    __syncthreads();

    for (int i = warp; i < Sm; i += 8) {
        for (int c = lane; c < HDm; c += 32)
            qrow[warp][c] = q[base + (long)i * Dm + c];
        __syncwarp();
        float lmax = -1e30f;
        for (int j = lane; j < Sm; j += 32) {
            float d = 0.0f;
            #pragma unroll
            for (int c = 0; c < HDm; c++) d += qrow[warp][c] * Ks[j * KPAD + c];
            att[warp][j] = d;
            lmax = fmaxf(lmax, d);
        }
        #pragma unroll
        for (int off = 16; off; off >>= 1)
            lmax = fmaxf(lmax, __shfl_xor_sync(0xffffffffu, lmax, off));
        float lsum = 0.0f;
        for (int j = lane; j < Sm; j += 32) {
            float e = expf(att[warp][j] - lmax);
            att[warp][j] = e;
            lsum += e;
        }
        #pragma unroll
        for (int off = 16; off; off >>= 1)
            lsum += __shfl_xor_sync(0xffffffffu, lsum, off);
        float inv = 1.0f / lsum;
        __syncwarp();
        for (int c = lane; c < HDm; c += 32) {
            float acc = 0.0f;
            for (int j = 0; j < Sm; j++) acc += att[warp][j] * Vs[j * KPAD + c];
            o[base + (long)i * Dm + c] = acc * inv;
        }
        __syncwarp();
    }
}

// ---------------- MoE routing: one block per group ----------------
__global__ void route_kernel(const float* __restrict__ h, const float* __restrict__ wr) {
    int n = blockIdx.x;                   // group
    __shared__ float wrs[Em * Dm];        // transposed: [e][c]
    __shared__ float tv[GSm][Km];
    __shared__ int   ti[GSm][Km];
    int tid = threadIdx.x, warp = tid >> 5, lane = tid & 31;

    for (int idx = tid; idx < Em * Dm; idx += blockDim.x) {
        int e = idx / Dm, c = idx % Dm;
        wrs[e * Dm + c] = wr[c * Em + e];
    }
    // init slot table for this group
    for (int s = tid; s < Em * CAPm; s += blockDim.x) {
        int e = s / CAPm, c = s % CAPm;
        g_slot_src[(e * NGm + n) * CAPm + c] = -1;
    }
    __syncthreads();

    for (int t = warp; t < GSm; t += 8) {
        const float* xr = h + (long)(n * GSm + t) * Dm;
        float a[Em];
        #pragma unroll
        for (int e = 0; e < Em; e++) a[e] = 0.0f;
        for (int c = lane; c < Dm; c += 32) {
            float xv = xr[c];
            #pragma unroll
            for (int e = 0; e < Em; e++) a[e] += xv * wrs[e * Dm + c];
        }
        #pragma unroll
        for (int e = 0; e < Em; e++)
            #pragma unroll
            for (int o = 16; o; o >>= 1) a[e] += __shfl_xor_sync(0xffffffffu, a[e], o);
        if (lane == 0) {
            float mx = a[0];
            #pragma unroll
            for (int e = 1; e < Em; e++) mx = fmaxf(mx, a[e]);
            float p[Em], sum = 0.0f;
            #pragma unroll
            for (int e = 0; e < Em; e++) { p[e] = expf(a[e] - mx); sum += p[e]; }
            float inv = 1.0f / sum;
            #pragma unroll
            for (int e = 0; e < Em; e++) p[e] *= inv;
            int i0 = 0;
            #pragma unroll
            for (int e = 1; e < Em; e++) if (p[e] > p[i0]) i0 = e;
            int i1 = (i0 == 0) ? 1 : 0;
            #pragma unroll
            for (int e = 0; e < Em; e++)
                if (e != i0 && p[e] > p[i1]) i1 = e;
            ti[t][0] = i0; tv[t][0] = p[i0];
            ti[t][1] = i1; tv[t][1] = p[i1];
        }
    }
    __syncthreads();

    if (tid == 0) {
        int cnt[Em];
        #pragma unroll
        for (int e = 0; e < Em; e++) cnt[e] = 0;
        for (int kk = 0; kk < Km; kk++) {
            for (int t = 0; t < GSm; t++) {
                int e = ti[t][kk];
                int pos = cnt[e]++;
                int gt = n * GSm + t;
                if (pos < CAPm) {
                    int row = (e * NGm + n) * CAPm + pos;
                    g_slot_src[row] = gt;
                    g_comb_idx[gt * Km + kk] = row;
                    g_comb_gate[gt * Km + kk] = tv[t][kk];
                } else {
                    g_comb_idx[gt * Km + kk] = -1;
                    g_comb_gate[gt * Km + kk] = 0.0f;
                }
            }
        }
    }
}

__global__ void gather_kernel(const float* __restrict__ h) {
    int i = blockIdx.x * blockDim.x + threadIdx.x;
    if (i >= TROWS * Dm) return;
    int row = i / Dm, c = i - row * Dm;
    int src = g_slot_src[row];
    g_buf[i] = (src >= 0) ? h[(long)src * Dm + c] : 0.0f;
}

__global__ void combine_kernel(float* __restrict__ x) {
    int i = blockIdx.x * blockDim.x + threadIdx.x;
    if (i >= NTOK * Dm) return;
    int t = i / Dm, c = i - t * Dm;
    float acc = 0.0f;
    #pragma unroll
    for (int kk = 0; kk < Km; kk++) {
        int r = g_comb_idx[t * Km + kk];
        if (r >= 0) acc += g_comb_gate[t * Km + kk] * g_y[(long)r * Dm + c];
    }
    x[i] += acc;
}

// ---------------- host orchestration ----------------
extern "C" void kernel_launch(void* const* d_in, const int* in_sizes, int n_in,
                              void* d_out, int out_size) {
    (void)in_sizes; (void)n_in; (void)out_size;
    const float* in_x     = (const float*)d_in[0];
    const float* posemb   = (const float*)d_in[1];
    const float* ln1_s    = (const float*)d_in[2];
    const float* ln1_b    = (const float*)d_in[3];
    const float* wq       = (const float*)d_in[4];
    const float* bq       = (const float*)d_in[5];
    const float* wk       = (const float*)d_in[6];
    const float* bk       = (const float*)d_in[7];
    const float* wv       = (const float*)d_in[8];
    const float* bv       = (const float*)d_in[9];
    const float* wo       = (const float*)d_in[10];
    const float* bo       = (const float*)d_in[11];
    const float* ln2_s    = (const float*)d_in[12];
    const float* ln2_b    = (const float*)d_in[13];
    const float* dw1      = (const float*)d_in[14];
    const float* db1      = (const float*)d_in[15];
    const float* dw2      = (const float*)d_in[16];
    const float* db2      = (const float*)d_in[17];
    const float* router_w = (const float*)d_in[18];
    const float* mw1      = (const float*)d_in[19];
    const float* mb1      = (const float*)d_in[20];
    const float* mw2      = (const float*)d_in[21];
    const float* mb2      = (const float*)d_in[22];
    const float* out_s    = (const float*)d_in[23];
    const float* out_b    = (const float*)d_in[24];
    float* out = (float*)d_out;

    float *x, *h, *q, *k, *v, *ao, *mlp, *buf, *hex, *y;
    cudaGetSymbolAddress((void**)&x,   g_x);
    cudaGetSymbolAddress((void**)&h,   g_h);
    cudaGetSymbolAddress((void**)&q,   g_q);
    cudaGetSymbolAddress((void**)&k,   g_k);
    cudaGetSymbolAddress((void**)&v,   g_v);
    cudaGetSymbolAddress((void**)&ao,  g_ao);
    cudaGetSymbolAddress((void**)&mlp, g_mlp);
    cudaGetSymbolAddress((void**)&buf, g_buf);
    cudaGetSymbolAddress((void**)&hex, g_hex);
    cudaGetSymbolAddress((void**)&y,   g_y);

    const int ATTN_SMEM = 2 * Sm * KPAD * (int)sizeof(float);
    cudaFuncSetAttribute(attn_kernel, cudaFuncAttributeMaxDynamicSharedMemorySize, ATTN_SMEM);

    const float qscale = 0.125f;   // 1/sqrt(64)

    addpos_kernel<<<(NTOK * Dm + 255) / 256, 256>>>(in_x, posemb, x);

    int di = 0, mi = 0;
    for (int l = 0; l < Lm; l++) {
        // attn block
        ln_kernel<<<NTOK, 256>>>(x, h, ln1_s + (size_t)l * Dm, ln1_b + (size_t)l * Dm);
        dim3 gdd(Dm / 128, NTOK / 128, 1);   // 6, 49
        sgemm_kernel<<<gdd, 256>>>(h, wq + (size_t)l * Dm * Dm, bq + (size_t)l * Dm, q,
                                   NTOK, Dm, Dm, 0, 0, 0, 0, qscale, 0, 0);
        sgemm_kernel<<<gdd, 256>>>(h, wk + (size_t)l * Dm * Dm, bk + (size_t)l * Dm, k,
                                   NTOK, Dm, Dm, 0, 0, 0, 0, 1.0f, 0, 0);
        sgemm_kernel<<<gdd, 256>>>(h, wv + (size_t)l * Dm * Dm, bv + (size_t)l * Dm, v,
                                   NTOK, Dm, Dm, 0, 0, 0, 0, 1.0f, 0, 0);
        attn_kernel<<<Bm * Hh, 256, ATTN_SMEM>>>(q, k, v, ao);
        sgemm_kernel<<<gdd, 256>>>(ao, wo + (size_t)l * Dm * Dm, bo + (size_t)l * Dm, x,
                                   NTOK, Dm, Dm, 0, 0, 0, 0, 1.0f, 0, 1);  // residual add

        // mlp / moe block
        ln_kernel<<<NTOK, 256>>>(x, h, ln2_s + (size_t)l * Dm, ln2_b + (size_t)l * Dm);
        if (l & 1) {  // MoE layers 1,3,5,7,9,11
            route_kernel<<<NGm, 256>>>(h, router_w + (size_t)mi * Dm * Em);
            gather_kernel<<<(TROWS * Dm + 255) / 256, 256>>>(h);
            dim3 g1(Mm / 128, (EROWS + 127) / 128, Em);   // 24, 13, 8
            sgemm_kernel<<<g1, 256>>>(buf, mw1 + (size_t)mi * Em * Dm * Mm,
                                      mb1 + (size_t)mi * Em * Mm, hex,
                                      EROWS, Dm, Mm,
                                      (long)EROWS * Dm, (long)Dm * Mm, Mm, (long)EROWS * Mm,
                                      1.0f, 1, 0);
            dim3 g2(Dm / 128, (EROWS + 127) / 128, Em);   // 6, 13, 8
            sgemm_kernel<<<g2, 256>>>(hex, mw2 + (size_t)mi * Em * Mm * Dm,
                                      mb2 + (size_t)mi * Em * Dm, y,
                                      EROWS, Mm, Dm,
                                      (long)EROWS * Mm, (long)Mm * Dm, Dm, (long)EROWS * Dm,
                                      1.0f, 0, 0);
            combine_kernel<<<(NTOK * Dm + 255) / 256, 256>>>(x);
            mi++;
        } else {
            dim3 g1(Mm / 128, NTOK / 128, 1);   // 24, 49
            sgemm_kernel<<<g1, 256>>>(h, dw1 + (size_t)di * Dm * Mm, db1 + (size_t)di * Mm, mlp,
                                      NTOK, Dm, Mm, 0, 0, 0, 0, 1.0f, 1, 0);
            dim3 g2(Dm / 128, NTOK / 128, 1);   // 6, 49
            sgemm_kernel<<<g2, 256>>>(mlp, dw2 + (size_t)di * Mm * Dm, db2 + (size_t)di * Dm, x,
                                      NTOK, Mm, Dm, 0, 0, 0, 0, 1.0f, 0, 1);  // residual add
            di++;
        }
    }

    ln_kernel<<<NTOK, 256>>>(x, out, out_s, out_b);
}

// round 4
// speedup vs baseline: 1.2878x; 1.2878x over previous
#include <cuda_runtime.h>
#include <math.h>
#include <stdint.h>

// ---------------- problem constants ----------------
#define Dm   768
#define Hh   12
#define HDm  64
#define Mm   3072
#define Lm   12
#define Em   8
#define Km   2
#define Bm   32
#define Sm   196
#define GSm  392
#define NGm  16
#define CAPm 98
#define NTOK (Bm*Sm)     // 6272
#define EROWS (NGm*CAPm) // 1568
#define TROWS (Em*EROWS) // 12544

// ---------------- scratch ----------------
__device__ float g_x  [(size_t)NTOK*Dm];
__device__ float g_h  [(size_t)NTOK*Dm];
__device__ float g_q  [(size_t)NTOK*Dm];
__device__ float g_k  [(size_t)NTOK*Dm];
__device__ float g_v  [(size_t)NTOK*Dm];
__device__ float g_ao [(size_t)NTOK*Dm];
__device__ float g_mlp[(size_t)NTOK*Mm];
__device__ float g_buf[(size_t)TROWS*Dm];
__device__ float g_hex[(size_t)TROWS*Mm];
__device__ float g_y  [(size_t)TROWS*Dm];
__device__ int   g_slot_src[TROWS];
__device__ int   g_comb_idx[NTOK*Km];
__device__ float g_comb_gate[NTOK*Km];

// ---------------- helpers ----------------
__device__ __forceinline__ float gelu_f(float x) {
    const float c = 0.7978845608028654f;
    float t = tanhf(c * (x + 0.044715f * x * x * x));
    return 0.5f * x * (1.0f + t);
}

__device__ __forceinline__ uint32_t smem_u32(const void* p) {
    uint32_t a;
    asm("{ .reg .u64 t; cvta.to.shared.u64 t, %1; cvt.u32.u64 %0, t; }" : "=r"(a) : "l"(p));
    return a;
}

__device__ __forceinline__ void cp16(uint32_t dst, const void* src, uint32_t sz) {
    asm volatile("cp.async.ca.shared.global [%0], [%1], 16, %2;"
                 :: "r"(dst), "l"(src), "r"(sz));
}
#define CP_COMMIT() asm volatile("cp.async.commit_group;" ::: "memory")
#define CP_WAIT(n)  asm volatile("cp.async.wait_group %0;" :: "n"(n) : "memory")

__device__ __forceinline__ void mma8(float* c, const uint32_t* a, const uint32_t* b) {
    asm volatile(
        "mma.sync.aligned.m16n8k8.row.col.f32.tf32.tf32.f32 "
        "{%0,%1,%2,%3},{%4,%5,%6,%7},{%8,%9},{%0,%1,%2,%3};"
        : "+f"(c[0]), "+f"(c[1]), "+f"(c[2]), "+f"(c[3])
        : "r"(a[0]), "r"(a[1]), "r"(a[2]), "r"(a[3]), "r"(b[0]), "r"(b[1]));
}

// 3xTF32 split: x = hi + lo (both tf32), hi = rna(x), lo = rna(x - hi)
__device__ __forceinline__ void split_tf32(float x, uint32_t& hi, uint32_t& lo) {
    asm("cvt.rna.tf32.f32 %0, %1;" : "=r"(hi) : "f"(x));
    float l = x - __uint_as_float(hi);
    asm("cvt.rna.tf32.f32 %0, %1;" : "=r"(lo) : "f"(l));
}

// ---------------- 3xTF32 mma.sync GEMM: C[N,P] = epi(A@W + bias) ----------------
#define APAD 36
#define BPAD 136
#define AB_FLOATS (128*APAD)   // 4608
#define BB_FLOATS (32*BPAD)    // 4352
#define GEMM_SMEM (2*(AB_FLOATS+BB_FLOATS)*4)  // 71680 bytes

__global__ void __launch_bounds__(256)
mma_gemm(const float* __restrict__ A, const float* __restrict__ W,
         const float* __restrict__ bias, float* __restrict__ C,
         int Nrows, int Kd, int Pc,
         long strA, long strW, long strBias, long strC,
         float alpha, int act, int accum) {
    int z = blockIdx.z;
    A += (long)z * strA; W += (long)z * strW; C += (long)z * strC;
    const float* Bp = bias + (long)z * strBias;

    extern __shared__ float sm_f[];
    float* Abuf = sm_f;                 // [2][AB_FLOATS]
    float* Bbuf = sm_f + 2 * AB_FLOATS; // [2][BB_FLOATS]
    uint32_t sA0 = smem_u32(Abuf), sB0 = smem_u32(Bbuf);

    int tid = threadIdx.x;
    int row0 = blockIdx.y * 128, col0 = blockIdx.x * 128;

    // staging maps
    int ar = tid >> 1, ak = (tid & 1) * 16;       // A: 128 rows x 32 cols
    int bk = tid >> 3, bn = (tid & 7) * 16;       // B: 32 rows x 128 cols
    const float* Ag = A + (long)(row0 + ar) * Kd + ak;
    const float* Wg = W + (long)bk * Pc + col0 + bn;
    uint32_t asz = ((row0 + ar) < Nrows) ? 16u : 0u;
    uint32_t adst = sA0 + (uint32_t)(ar * APAD + ak) * 4u;
    uint32_t bdst = sB0 + (uint32_t)(bk * BPAD + bn) * 4u;

    int nk = Kd / 32;

    // prologue: stage chunk 0 into buffer 0
    #pragma unroll
    for (int j = 0; j < 4; j++) cp16(adst + j * 16, Ag + j * 4, asz);
    #pragma unroll
    for (int j = 0; j < 4; j++) cp16(bdst + j * 16, Wg + j * 4, 16);
    CP_COMMIT();

    int warp = tid >> 5, lane = tid & 31;
    int wm = (warp & 3) * 32, wn = (warp >> 2) * 64;
    int gid = lane >> 2, tig = lane & 3;

    float acc[2][8][4];
    #pragma unroll
    for (int mt = 0; mt < 2; mt++)
        #pragma unroll
        for (int nt = 0; nt < 8; nt++)
            #pragma unroll
            for (int r = 0; r < 4; r++) acc[mt][nt][r] = 0.0f;

    for (int i = 0; i < nk; i++) {
        int b = i & 1;
        if (i + 1 < nk) {
            int nb = b ^ 1;
            const float* ga = Ag + (i + 1) * 32;
            const float* gb = Wg + (long)(i + 1) * 32 * Pc;
            uint32_t da = adst + (uint32_t)(nb * AB_FLOATS) * 4u;
            uint32_t db = bdst + (uint32_t)(nb * BB_FLOATS) * 4u;
            #pragma unroll
            for (int j = 0; j < 4; j++) cp16(da + j * 16, ga + j * 4, asz);
            #pragma unroll
            for (int j = 0; j < 4; j++) cp16(db + j * 16, gb + j * 4, 16);
            CP_COMMIT();
            CP_WAIT(1);
        } else {
            CP_WAIT(0);
        }
        __syncthreads();

        const float* As = Abuf + b * AB_FLOATS;
        const float* Bs = Bbuf + b * BB_FLOATS;
        #pragma unroll
        for (int kq = 0; kq < 32; kq += 8) {
            uint32_t afh[2][4], afl[2][4];
            #pragma unroll
            for (int mt = 0; mt < 2; mt++) {
                int base = (wm + mt * 16 + gid) * APAD + kq + tig;
                split_tf32(As[base],                afh[mt][0], afl[mt][0]);
                split_tf32(As[base + 8 * APAD],     afh[mt][1], afl[mt][1]);
                split_tf32(As[base + 4],            afh[mt][2], afl[mt][2]);
                split_tf32(As[base + 8 * APAD + 4], afh[mt][3], afl[mt][3]);
            }
            uint32_t bfh[8][2], bfl[8][2];
            #pragma unroll
            for (int nt = 0; nt < 8; nt++) {
                int base = (kq + tig) * BPAD + wn + nt * 8 + gid;
                split_tf32(Bs[base],            bfh[nt][0], bfl[nt][0]);
                split_tf32(Bs[base + 4 * BPAD], bfh[nt][1], bfl[nt][1]);
            }
            #pragma unroll
            for (int mt = 0; mt < 2; mt++)
                #pragma unroll
                for (int nt = 0; nt < 8; nt++) {
                    mma8(acc[mt][nt], afh[mt], bfl[nt]);   // hi*lo
                    mma8(acc[mt][nt], afl[mt], bfh[nt]);   // lo*hi
                    mma8(acc[mt][nt], afh[mt], bfh[nt]);   // hi*hi
                }
        }
        __syncthreads();
    }

    // epilogue: fused bias + alpha + gelu + optional residual accumulate
    #pragma unroll
    for (int mt = 0; mt < 2; mt++) {
        int r0 = row0 + wm + mt * 16 + gid;
        #pragma unroll
        for (int half = 0; half < 2; half++) {
            int gr = r0 + half * 8;
            if (gr >= Nrows) continue;
            float* Crow = C + (long)gr * Pc;
            #pragma unroll
            for (int nt = 0; nt < 8; nt++) {
                int gc = col0 + wn + nt * 8 + 2 * tig;
                float2 bv = *reinterpret_cast<const float2*>(Bp + gc);
                float v0 = (acc[mt][nt][half * 2 + 0] + bv.x) * alpha;
                float v1 = (acc[mt][nt][half * 2 + 1] + bv.y) * alpha;
                if (act) { v0 = gelu_f(v0); v1 = gelu_f(v1); }
                if (accum) {
                    float2 o = *reinterpret_cast<float2*>(Crow + gc);
                    v0 += o.x; v1 += o.y;
                }
                *reinterpret_cast<float2*>(Crow + gc) = make_float2(v0, v1);
            }
        }
    }
}

// ---------------- elementwise ----------------
__global__ void addpos_kernel(const float* __restrict__ x, const float* __restrict__ pe,
                              float* __restrict__ out) {
    int i = blockIdx.x * blockDim.x + threadIdx.x;
    if (i < NTOK * Dm) out[i] = x[i] + pe[i % (Sm * Dm)];
}

__device__ __forceinline__ float block_reduce_sum(float v) {
    __shared__ float sh[33];
    int lane = threadIdx.x & 31, w = threadIdx.x >> 5;
    #pragma unroll
    for (int o = 16; o; o >>= 1) v += __shfl_xor_sync(0xffffffffu, v, o);
    if (lane == 0) sh[w] = v;
    __syncthreads();
    int nw = blockDim.x >> 5;
    float r = (threadIdx.x < nw) ? sh[threadIdx.x] : 0.0f;
    if (w == 0) {
        #pragma unroll
        for (int o = 16; o; o >>= 1) r += __shfl_xor_sync(0xffffffffu, r, o);
        if (lane == 0) sh[32] = r;
    }
    __syncthreads();
    float out = sh[32];
    __syncthreads();
    return out;
}

__global__ void ln_kernel(const float* __restrict__ in, float* __restrict__ out,
                          const float* __restrict__ s, const float* __restrict__ b) {
    int t = blockIdx.x;
    const float* xr = in + (size_t)t * Dm;
    float sum = 0.0f;
    for (int i = threadIdx.x; i < Dm; i += blockDim.x) sum += xr[i];
    float mu = block_reduce_sum(sum) * (1.0f / Dm);
    float vs = 0.0f;
    for (int i = threadIdx.x; i < Dm; i += blockDim.x) { float d = xr[i] - mu; vs += d * d; }
    float var = block_reduce_sum(vs) * (1.0f / Dm);
    float inv = rsqrtf(var + 1e-6f);
    float* orow = out + (size_t)t * Dm;
    for (int i = threadIdx.x; i < Dm; i += blockDim.x)
        orow[i] = (xr[i] - mu) * inv * s[i] + b[i];
}

// ---------------- attention ----------------
#define KPAD (HDm + 1)
__global__ void attn_kernel(const float* __restrict__ q, const float* __restrict__ k,
                            const float* __restrict__ v, float* __restrict__ o) {
    extern __shared__ float sm[];
    float* Ks = sm;
    float* Vs = sm + Sm * KPAD;
    __shared__ float att[8][Sm];
    __shared__ float qrow[8][HDm];

    int bh = blockIdx.x;
    int b = bh / Hh, h = bh % Hh;
    int tid = threadIdx.x, warp = tid >> 5, lane = tid & 31;
    const long base = (long)(b * Sm) * Dm + h * HDm;

    for (int idx = tid; idx < Sm * HDm; idx += blockDim.x) {
        int j = idx >> 6, c = idx & 63;
        Ks[j * KPAD + c] = k[base + (long)j * Dm + c];
        Vs[j * KPAD + c] = v[base + (long)j * Dm + c];
    }
    __syncthreads();

    for (int i = warp; i < Sm; i += 8) {
        for (int c = lane; c < HDm; c += 32) qrow[warp][c] = q[base + (long)i * Dm + c];
        __syncwarp();
        float lmax = -1e30f;
        for (int j = lane; j < Sm; j += 32) {
            float d = 0.0f;
            #pragma unroll
            for (int c = 0; c < HDm; c++) d += qrow[warp][c] * Ks[j * KPAD + c];
            att[warp][j] = d;
            lmax = fmaxf(lmax, d);
        }
        #pragma unroll
        for (int off = 16; off; off >>= 1)
            lmax = fmaxf(lmax, __shfl_xor_sync(0xffffffffu, lmax, off));
        float lsum = 0.0f;
        for (int j = lane; j < Sm; j += 32) {
            float e = expf(att[warp][j] - lmax);
            att[warp][j] = e;
            lsum += e;
        }
        #pragma unroll
        for (int off = 16; off; off >>= 1)
            lsum += __shfl_xor_sync(0xffffffffu, lsum, off);
        float inv = 1.0f / lsum;
        __syncwarp();
        for (int c = lane; c < HDm; c += 32) {
            float acc = 0.0f;
            for (int j = 0; j < Sm; j++) acc += att[warp][j] * Vs[j * KPAD + c];
            o[base + (long)i * Dm + c] = acc * inv;
        }
        __syncwarp();
    }
}

// ---------------- MoE routing ----------------
__global__ void route_kernel(const float* __restrict__ h, const float* __restrict__ wr) {
    int n = blockIdx.x;
    __shared__ float wrs[Em * Dm];
    __shared__ float tv[GSm][Km];
    __shared__ int   ti[GSm][Km];
    int tid = threadIdx.x, warp = tid >> 5, lane = tid & 31;

    for (int idx = tid; idx < Em * Dm; idx += blockDim.x) {
        int e = idx / Dm, c = idx % Dm;
        wrs[e * Dm + c] = wr[c * Em + e];
    }
    for (int s = tid; s < Em * CAPm; s += blockDim.x) {
        int e = s / CAPm, c = s % CAPm;
        g_slot_src[(e * NGm + n) * CAPm + c] = -1;
    }
    __syncthreads();

    for (int t = warp; t < GSm; t += 8) {
        const float* xr = h + (long)(n * GSm + t) * Dm;
        float a[Em];
        #pragma unroll
        for (int e = 0; e < Em; e++) a[e] = 0.0f;
        for (int c = lane; c < Dm; c += 32) {
            float xv = xr[c];
            #pragma unroll
            for (int e = 0; e < Em; e++) a[e] += xv * wrs[e * Dm + c];
        }
        #pragma unroll
        for (int e = 0; e < Em; e++)
            #pragma unroll
            for (int o = 16; o; o >>= 1) a[e] += __shfl_xor_sync(0xffffffffu, a[e], o);
        if (lane == 0) {
            float mx = a[0];
            #pragma unroll
            for (int e = 1; e < Em; e++) mx = fmaxf(mx, a[e]);
            float p[Em], sum = 0.0f;
            #pragma unroll
            for (int e = 0; e < Em; e++) { p[e] = expf(a[e] - mx); sum += p[e]; }
            float inv = 1.0f / sum;
            #pragma unroll
            for (int e = 0; e < Em; e++) p[e] *= inv;
            int i0 = 0;
            #pragma unroll
            for (int e = 1; e < Em; e++) if (p[e] > p[i0]) i0 = e;
            int i1 = (i0 == 0) ? 1 : 0;
            #pragma unroll
            for (int e = 0; e < Em; e++) if (e != i0 && p[e] > p[i1]) i1 = e;
            ti[t][0] = i0; tv[t][0] = p[i0];
            ti[t][1] = i1; tv[t][1] = p[i1];
        }
    }
    __syncthreads();

    if (tid == 0) {
        int cnt[Em];
        #pragma unroll
        for (int e = 0; e < Em; e++) cnt[e] = 0;
        for (int kk = 0; kk < Km; kk++) {
            for (int t = 0; t < GSm; t++) {
                int e = ti[t][kk];
                int pos = cnt[e]++;
                int gt = n * GSm + t;
                if (pos < CAPm) {
                    int row = (e * NGm + n) * CAPm + pos;
                    g_slot_src[row] = gt;
                    g_comb_idx[gt * Km + kk] = row;
                    g_comb_gate[gt * Km + kk] = tv[t][kk];
                } else {
                    g_comb_idx[gt * Km + kk] = -1;
                    g_comb_gate[gt * Km + kk] = 0.0f;
                }
            }
        }
    }
}

__global__ void gather_kernel(const float* __restrict__ h) {
    int i = blockIdx.x * blockDim.x + threadIdx.x;
    if (i >= TROWS * Dm) return;
    int row = i / Dm, c = i - row * Dm;
    int src = g_slot_src[row];
    g_buf[i] = (src >= 0) ? h[(long)src * Dm + c] : 0.0f;
}

__global__ void combine_kernel(float* __restrict__ x) {
    int i = blockIdx.x * blockDim.x + threadIdx.x;
    if (i >= NTOK * Dm) return;
    int t = i / Dm, c = i - t * Dm;
    float acc = 0.0f;
    #pragma unroll
    for (int kk = 0; kk < Km; kk++) {
        int r = g_comb_idx[t * Km + kk];
        if (r >= 0) acc += g_comb_gate[t * Km + kk] * g_y[(long)r * Dm + c];
    }
    x[i] += acc;
}

// ---------------- host ----------------
extern "C" void kernel_launch(void* const* d_in, const int* in_sizes, int n_in,
                              void* d_out, int out_size) {
    (void)in_sizes; (void)n_in; (void)out_size;
    const float* in_x     = (const float*)d_in[0];
    const float* posemb   = (const float*)d_in[1];
    const float* ln1_s    = (const float*)d_in[2];
    const float* ln1_b    = (const float*)d_in[3];
    const float* wq       = (const float*)d_in[4];
    const float* bq       = (const float*)d_in[5];
    const float* wk       = (const float*)d_in[6];
    const float* bk       = (const float*)d_in[7];
    const float* wv       = (const float*)d_in[8];
    const float* bv       = (const float*)d_in[9];
    const float* wo       = (const float*)d_in[10];
    const float* bo       = (const float*)d_in[11];
    const float* ln2_s    = (const float*)d_in[12];
    const float* ln2_b    = (const float*)d_in[13];
    const float* dw1      = (const float*)d_in[14];
    const float* db1      = (const float*)d_in[15];
    const float* dw2      = (const float*)d_in[16];
    const float* db2      = (const float*)d_in[17];
    const float* router_w = (const float*)d_in[18];
    const float* mw1      = (const float*)d_in[19];
    const float* mb1      = (const float*)d_in[20];
    const float* mw2      = (const float*)d_in[21];
    const float* mb2      = (const float*)d_in[22];
    const float* out_s    = (const float*)d_in[23];
    const float* out_b    = (const float*)d_in[24];
    float* out = (float*)d_out;

    float *x, *h, *q, *k, *v, *ao, *mlp, *buf, *hex, *y;
    cudaGetSymbolAddress((void**)&x,   g_x);
    cudaGetSymbolAddress((void**)&h,   g_h);
    cudaGetSymbolAddress((void**)&q,   g_q);
    cudaGetSymbolAddress((void**)&k,   g_k);
    cudaGetSymbolAddress((void**)&v,   g_v);
    cudaGetSymbolAddress((void**)&ao,  g_ao);
    cudaGetSymbolAddress((void**)&mlp, g_mlp);
    cudaGetSymbolAddress((void**)&buf, g_buf);
    cudaGetSymbolAddress((void**)&hex, g_hex);
    cudaGetSymbolAddress((void**)&y,   g_y);

    const int ATTN_SMEM = 2 * Sm * KPAD * (int)sizeof(float);
    cudaFuncSetAttribute(attn_kernel, cudaFuncAttributeMaxDynamicSharedMemorySize, ATTN_SMEM);
    cudaFuncSetAttribute(mma_gemm, cudaFuncAttributeMaxDynamicSharedMemorySize, GEMM_SMEM);

    const float qscale = 0.125f;

    addpos_kernel<<<(NTOK * Dm + 255) / 256, 256>>>(in_x, posemb, x);

    int di = 0, mi = 0;
    for (int l = 0; l < Lm; l++) {
        ln_kernel<<<NTOK, 256>>>(x, h, ln1_s + (size_t)l * Dm, ln1_b + (size_t)l * Dm);
        dim3 gdd(Dm / 128, NTOK / 128, 1);   // 6, 49
        mma_gemm<<<gdd, 256, GEMM_SMEM>>>(h, wq + (size_t)l * Dm * Dm, bq + (size_t)l * Dm, q,
                                          NTOK, Dm, Dm, 0, 0, 0, 0, qscale, 0, 0);
        mma_gemm<<<gdd, 256, GEMM_SMEM>>>(h, wk + (size_t)l * Dm * Dm, bk + (size_t)l * Dm, k,
                                          NTOK, Dm, Dm, 0, 0, 0, 0, 1.0f, 0, 0);
        mma_gemm<<<gdd, 256, GEMM_SMEM>>>(h, wv + (size_t)l * Dm * Dm, bv + (size_t)l * Dm, v,
                                          NTOK, Dm, Dm, 0, 0, 0, 0, 1.0f, 0, 0);
        attn_kernel<<<Bm * Hh, 256, ATTN_SMEM>>>(q, k, v, ao);
        mma_gemm<<<gdd, 256, GEMM_SMEM>>>(ao, wo + (size_t)l * Dm * Dm, bo + (size_t)l * Dm, x,
                                          NTOK, Dm, Dm, 0, 0, 0, 0, 1.0f, 0, 1);

        ln_kernel<<<NTOK, 256>>>(x, h, ln2_s + (size_t)l * Dm, ln2_b + (size_t)l * Dm);
        if (l & 1) {
            route_kernel<<<NGm, 256>>>(h, router_w + (size_t)mi * Dm * Em);
            gather_kernel<<<(TROWS * Dm + 255) / 256, 256>>>(h);
            dim3 g1(Mm / 128, (EROWS + 127) / 128, Em);   // 24, 13, 8
            mma_gemm<<<g1, 256, GEMM_SMEM>>>(buf, mw1 + (size_t)mi * Em * Dm * Mm,
                                             mb1 + (size_t)mi * Em * Mm, hex,
                                             EROWS, Dm, Mm,
                                             (long)EROWS * Dm, (long)Dm * Mm, Mm, (long)EROWS * Mm,
                                             1.0f, 1, 0);
            dim3 g2(Dm / 128, (EROWS + 127) / 128, Em);   // 6, 13, 8
            mma_gemm<<<g2, 256, GEMM_SMEM>>>(hex, mw2 + (size_t)mi * Em * Mm * Dm,
                                             mb2 + (size_t)mi * Em * Dm, y,
                                             EROWS, Mm, Dm,
                                             (long)EROWS * Mm, (long)Mm * Dm, Dm, (long)EROWS * Dm,
                                             1.0f, 0, 0);
            combine_kernel<<<(NTOK * Dm + 255) / 256, 256>>>(x);
            mi++;
        } else {
            dim3 g1(Mm / 128, NTOK / 128, 1);   // 24, 49
            mma_gemm<<<g1, 256, GEMM_SMEM>>>(h, dw1 + (size_t)di * Dm * Mm, db1 + (size_t)di * Mm,
                                             mlp, NTOK, Dm, Mm, 0, 0, 0, 0, 1.0f, 1, 0);
            dim3 g2(Dm / 128, NTOK / 128, 1);   // 6, 49
            mma_gemm<<<g2, 256, GEMM_SMEM>>>(mlp, dw2 + (size_t)di * Mm * Dm, db2 + (size_t)di * Dm,
                                             x, NTOK, Mm, Dm, 0, 0, 0, 0, 1.0f, 0, 1);
            di++;
        }
    }

    ln_kernel<<<NTOK, 256>>>(x, out, out_s, out_b);
}